// round 17
// baseline (speedup 1.0000x reference)
#include <cuda_runtime.h>
#include <cuda_bf16.h>
#include <cstdint>
#include <math.h>

#define N_   128
#define T_   32
#define TCAP 33
#define D_   400
#define WE_  512
#define H_   1024
#define H4_  4096
#define V_   10000
#define L_   16
#define NBLK 128
#define NBX  79
#define NLSE (NBX * 2)

// ---------------- device scratch ----------------
__device__ float g_A[N_ * H_ * L_];                       // [n][h][l]
__device__ float g_h0[N_ * H_];
__device__ float g_xproj[(size_t)N_ * T_ * H4_];          // permuted: [row][blk][32]
__device__ float g_w[N_ * L_];
__device__ float2 g_lsep[(size_t)N_ * T_ * NLSE];
__device__ float g_stgt[N_ * T_];
__device__ __align__(128) unsigned g_flags[NBLK * 8];     // 1 flag / 32B sector

// bf16 operands
__device__ __nv_bfloat16 gb_Wemb[(size_t)V_ * WE_];
__device__ __nv_bfloat16 gb_Wx[(size_t)WE_ * H4_];
__device__ __nv_bfloat16 gb_Wh[(size_t)H_ * H4_];
__device__ __nv_bfloat16 gb_Wattn[(size_t)H_ * H4_];
__device__ __nv_bfloat16 gb_Wv[(size_t)H_ * V_];
__device__ __nv_bfloat16 gb_At[N_ * L_ * H_];
__device__ __nv_bfloat16 gb_hbuf[2][N_ * H_];
__device__ __nv_bfloat16 gb_hn[N_ * T_ * H_];
__device__ __nv_bfloat16 gb_Pp[(size_t)N_ * L_ * H4_];    // [blk][n][c32][l] bf16

extern __shared__ char sm_raw[];

// fast transcendentals (MUFU)
__device__ __forceinline__ float tanhfast(float x) {
    float y; asm("tanh.approx.f32 %0, %1;" : "=f"(y) : "f"(x)); return y;
}
__device__ __forceinline__ float sigfast(float x) {
    return fmaf(0.5f, tanhfast(0.5f * x), 0.5f);
}

// ---------------- merged prep: init + f2b + kA in ONE kernel ----------------
#define R0 640000u
#define R1 (R0 + 262144u)
#define R2 (R1 + 524288u)
#define R3 (R2 + 524288u)
#define R4 (R3 + 1280000u)
#define F2B_BLKS ((R4 + 255u) / 256u)
#define PREP_BLKS (F2B_BLKS + NBLK)

__global__ __launch_bounds__(256) void prep_all(const float* __restrict__ Wemb,
                                                const float* __restrict__ Wx,
                                                const float* __restrict__ Wh,
                                                const float* __restrict__ Wattn,
                                                const float* __restrict__ Wv,
                                                const float* __restrict__ feat,
                                                const float* __restrict__ Wp,
                                                const float* __restrict__ bp,
                                                float* out) {
    __shared__ float fsh[D_ * L_];
    if (blockIdx.x < F2B_BLKS) {
        if (blockIdx.x == 0) {
            if (threadIdx.x == 0) out[0] = 0.0f;
            for (int i = threadIdx.x; i < NBLK * 8; i += 256) g_flags[i] = 0u;
        }
        unsigned i8 = blockIdx.x * 256 + threadIdx.x;
        const float* s; __nv_bfloat16* d; unsigned base;
        if (i8 < R0)      { s = Wemb;  d = gb_Wemb;  base = 0; }
        else if (i8 < R1) { s = Wx;    d = gb_Wx;    base = R0; }
        else if (i8 < R2) { s = Wh;    d = gb_Wh;    base = R1; }
        else if (i8 < R3) { s = Wattn; d = gb_Wattn; base = R2; }
        else if (i8 < R4) { s = Wv;    d = gb_Wv;    base = R3; }
        else return;
        size_t off = (size_t)(i8 - base) * 8;
        float4 v0 = *(const float4*)(s + off);
        float4 v1 = *(const float4*)(s + off + 4);
        union { __nv_bfloat162 h2[4]; uint4 u; } o;
        o.h2[0] = __floats2bfloat162_rn(v0.x, v0.y);
        o.h2[1] = __floats2bfloat162_rn(v0.z, v0.w);
        o.h2[2] = __floats2bfloat162_rn(v1.x, v1.y);
        o.h2[3] = __floats2bfloat162_rn(v1.z, v1.w);
        *(uint4*)(d + off) = o.u;
        return;
    }
    // ---- kA part ----
    int n = blockIdx.x - F2B_BLKS;
    const float* f = feat + (size_t)n * D_ * L_;
    for (int i = threadIdx.x; i < D_ * L_; i += 256) fsh[i] = f[i];
    __syncthreads();
    for (int h = threadIdx.x; h < H_; h += 256) {
        float acc[L_];
        float bb = bp[h];
#pragma unroll
        for (int l = 0; l < L_; l++) acc[l] = bb;
        for (int d = 0; d < D_; d++) {
            float wv = Wp[d * H_ + h];
            const float* fr = &fsh[d * L_];
#pragma unroll
            for (int l = 0; l < L_; l++) acc[l] = fmaf(fr[l], wv, acc[l]);
        }
        float s = 0.0f;
        float* Ar = g_A + ((size_t)n * H_ + h) * L_;
#pragma unroll
        for (int l = 0; l < L_; l++) {
            Ar[l] = acc[l];
            gb_At[((size_t)n * L_ + l) * H_ + h] = __float2bfloat16_rn(acc[l]);
            s += acc[l];
        }
        float h0 = s * (1.0f / 16.0f);
        g_h0[n * H_ + h] = h0;
        gb_hbuf[0][n * H_ + h] = __float2bfloat16_rn(h0);
    }
}

// ================= BF16 mma GEMM core (2-stage, static smem) =================
__device__ __forceinline__ void ldsm4(uint32_t a, unsigned& r0, unsigned& r1,
                                      unsigned& r2, unsigned& r3) {
    asm volatile("ldmatrix.sync.aligned.m8n8.x4.shared.b16 {%0,%1,%2,%3}, [%4];"
                 : "=r"(r0), "=r"(r1), "=r"(r2), "=r"(r3) : "r"(a));
}
__device__ __forceinline__ void ldsm4t(uint32_t a, unsigned& r0, unsigned& r1,
                                       unsigned& r2, unsigned& r3) {
    asm volatile("ldmatrix.sync.aligned.m8n8.x4.trans.shared.b16 {%0,%1,%2,%3}, [%4];"
                 : "=r"(r0), "=r"(r1), "=r"(r2), "=r"(r3) : "r"(a));
}
__device__ __forceinline__ void bmma(float* c, const unsigned* a,
                                     unsigned b0, unsigned b1) {
    asm volatile("mma.sync.aligned.m16n8k16.row.col.f32.bf16.bf16.f32 "
                 "{%0,%1,%2,%3},{%4,%5,%6,%7},{%8,%9},{%0,%1,%2,%3};"
                 : "+f"(c[0]), "+f"(c[1]), "+f"(c[2]), "+f"(c[3])
                 : "r"(a[0]), "r"(a[1]), "r"(a[2]), "r"(a[3]), "r"(b0), "r"(b1));
}
__device__ __forceinline__ void cpa16(uint32_t dst, const void* src) {
    asm volatile("cp.async.cg.shared.global [%0], [%1], 16;" ::"r"(dst), "l"(src));
}
__device__ __forceinline__ void cpa16z(uint32_t dst, const void* src, unsigned sz) {
    asm volatile("cp.async.cg.shared.global [%0], [%1], 16, %2;"
                 ::"r"(dst), "l"(src), "r"(sz));
}
__device__ __forceinline__ void cp_commit() { asm volatile("cp.async.commit_group;"); }
__device__ __forceinline__ void cp_wait1() { asm volatile("cp.async.wait_group 1;"); }
__device__ __forceinline__ void cp_wait0() { asm volatile("cp.async.wait_group 0;"); }

struct BfgLoader {
    const __nv_bfloat16 *a0, *a1, *b0, *b1;
    uint32_t aoff0, aoff1, boff0, boff1;
    size_t bstep;
    unsigned bsz;
    __device__ __forceinline__ void issue(int it, uint32_t dA, uint32_t dB) const {
        cpa16(dA + aoff0, a0 + it * 32);
        cpa16(dA + aoff1, a1 + it * 32);
        cpa16z(dB + boff0, b0 + (size_t)it * bstep, bsz);
        cpa16z(dB + boff1, b1 + (size_t)it * bstep, bsz);
    }
};

__device__ __forceinline__ void bfg_compute(uint32_t bA, uint32_t bB,
                                            int lane, int wm, int wn,
                                            float acc[2][8][4]) {
    const int l15 = lane & 15, l7 = lane & 7, lhi = lane >> 4;
    const int mA0 = wm * 32 + l15, mA1 = mA0 + 16;
    const uint32_t aR0 = (uint32_t)mA0 * 128, aR1 = (uint32_t)mA1 * 128;
    const int a70 = mA0 & 7, a71 = mA1 & 7;
    const uint32_t bRk = (uint32_t)l15 * 256;
#pragma unroll
    for (int ks = 0; ks < 2; ks++) {
        int c = ks * 2 + lhi;
        unsigned af0[4], af1[4];
        ldsm4(bA + aR0 + (uint32_t)(((c ^ a70) & 7) << 4),
              af0[0], af0[1], af0[2], af0[3]);
        ldsm4(bA + aR1 + (uint32_t)(((c ^ a71) & 7) << 4),
              af1[0], af1[1], af1[2], af1[3]);
#pragma unroll
        for (int p = 0; p < 4; p++) {
            unsigned bf0, bf1, bf2, bf3;
            int g = wn * 8 + p * 2 + lhi;
            ldsm4t(bB + (uint32_t)(ks * 16) * 256 + bRk + (uint32_t)((g ^ l7) << 4),
                   bf0, bf1, bf2, bf3);
            bmma(acc[0][2 * p],     af0, bf0, bf1);
            bmma(acc[0][2 * p + 1], af0, bf2, bf3);
            bmma(acc[1][2 * p],     af1, bf0, bf1);
            bmma(acc[1][2 * p + 1], af1, bf2, bf3);
        }
    }
}

__device__ __forceinline__ void bfg_run(const BfgLoader& ld, int nIter,
                                        uint32_t sA0, uint32_t sB0,
                                        int lane, int wm, int wn,
                                        float acc[2][8][4]) {
    ld.issue(0, sA0, sB0);
    cp_commit();
    for (int it = 0; it < nIter; it++) {
        uint32_t bA = sA0 + (uint32_t)(it & 1) * 16384;
        uint32_t bB = sB0 + (uint32_t)(it & 1) * 8192;
        if (it + 1 < nIter) {
            ld.issue(it + 1, sA0 + (uint32_t)((it + 1) & 1) * 16384,
                     sB0 + (uint32_t)((it + 1) & 1) * 8192);
            cp_commit();
            cp_wait1();
        } else {
            cp_wait0();
        }
        __syncthreads();
        bfg_compute(bA, bB, lane, wm, wn, acc);
        __syncthreads();
    }
}

struct BfgIdx {
    int tid, lane, wid, wm, wn, am, ag, bks, bg;
    uint32_t aoff0, aoff1, boff0, boff1;
    __device__ __forceinline__ BfgIdx() {
        tid = threadIdx.x; lane = tid & 31; wid = tid >> 5;
        wm = wid >> 1; wn = wid & 1;
        am = tid >> 2; ag = tid & 3;
        bks = tid >> 4; bg = tid & 15;
        aoff0 = (uint32_t)am * 128 + (uint32_t)(((ag ^ (am & 7)) & 7) << 4);
        aoff1 = aoff0 + 64 * 128;
        boff0 = (uint32_t)bks * 256 + (uint32_t)((bg ^ (bks & 7)) << 4);
        boff1 = boff0 + 16 * 256;
    }
};

#define BFG_SMEM                                                               \
    __shared__ __align__(16) char sAm[2][16384];                               \
    __shared__ __align__(16) char sBm[2][8192];                                \
    uint32_t sA0 = (uint32_t)__cvta_generic_to_shared(sAm);                    \
    uint32_t sB0 = (uint32_t)__cvta_generic_to_shared(sBm);

// ---- merged: xproj = W_embed[cap] @ Wx + b (permuted out)  AND  P = A^T @ Wattn ----
__global__ __launch_bounds__(256) void gemm_embedP(const int* __restrict__ captions,
                                                   const float* __restrict__ bias) {
    BFG_SMEM;
    BfgIdx ix;
    float acc[2][8][4] = {};
    if (blockIdx.x < 1024) {
        // ======== embed part ========
        int row0 = (blockIdx.x >> 5) * 128, col0 = (blockIdx.x & 31) * 128;
        int r0i = row0 + ix.am, r1i = r0i + 64;
        BfgLoader ld;
        ld.a0 = gb_Wemb + (size_t)captions[(r0i >> 5) * TCAP + (r0i & 31)] * WE_ + ix.ag * 8;
        ld.a1 = gb_Wemb + (size_t)captions[(r1i >> 5) * TCAP + (r1i & 31)] * WE_ + ix.ag * 8;
        ld.b0 = gb_Wx + (size_t)ix.bks * H4_ + col0 + ix.bg * 8;
        ld.b1 = ld.b0 + (size_t)16 * H4_;
        ld.aoff0 = ix.aoff0; ld.aoff1 = ix.aoff1; ld.boff0 = ix.boff0; ld.boff1 = ix.boff1;
        ld.bstep = (size_t)32 * H4_; ld.bsz = 16;
        bfg_run(ld, WE_ / 32, sA0, sB0, ix.lane, ix.wm, ix.wn, acc);
        int eg = ix.lane >> 2, ec = (ix.lane & 3) * 2;
#pragma unroll
        for (int mt = 0; mt < 2; mt++)
#pragma unroll
            for (int nt = 0; nt < 8; nt++) {
                int row = row0 + ix.wm * 32 + mt * 16 + eg;
                int col = col0 + ix.wn * 64 + nt * 8 + ec;
                float b0v = bias[col], b1v = bias[col + 1];
                // permuted store: col -> (bblk, c32)
                int gate = col >> 10, rem = col & 1023;
                int bblk = rem >> 3, c32 = gate * 8 + (rem & 7);
                size_t base0 = ((size_t)row * NBLK + bblk) * 32 + c32;
                size_t base1 = ((size_t)(row + 8) * NBLK + bblk) * 32 + c32;
                *(float2*)&g_xproj[base0] =
                    make_float2(acc[mt][nt][0] + b0v, acc[mt][nt][1] + b1v);
                *(float2*)&g_xproj[base1] =
                    make_float2(acc[mt][nt][2] + b0v, acc[mt][nt][3] + b1v);
            }
    } else {
        // ======== P part ========
        int idx = blockIdx.x - 1024;
        int row0 = (idx >> 5) * 128, col0 = (idx & 31) * 128;
        BfgLoader ld;
        ld.a0 = gb_At + (size_t)(row0 + ix.am) * H_ + ix.ag * 8;
        ld.a1 = ld.a0 + (size_t)64 * H_;
        ld.b0 = gb_Wattn + (size_t)ix.bks * H4_ + col0 + ix.bg * 8;
        ld.b1 = ld.b0 + (size_t)16 * H4_;
        ld.aoff0 = ix.aoff0; ld.aoff1 = ix.aoff1; ld.boff0 = ix.boff0; ld.boff1 = ix.boff1;
        ld.bstep = (size_t)32 * H4_; ld.bsz = 16;
        bfg_run(ld, H_ / 32, sA0, sB0, ix.lane, ix.wm, ix.wn, acc);
        int eg = ix.lane >> 2, ec = (ix.lane & 3) * 2;
#pragma unroll
        for (int mt = 0; mt < 2; mt++)
#pragma unroll
            for (int nt = 0; nt < 8; nt++) {
                int row = row0 + ix.wm * 32 + mt * 16 + eg;    // = n*16 + l, l in 0..7
                int col = col0 + ix.wn * 64 + nt * 8 + ec;
                int n = row >> 4, l = row & 15;
                int gate = col >> 10, rem = col & 1023;
                int bblk = rem >> 3, c32 = gate * 8 + (rem & 7);
                size_t base = (((size_t)bblk * 128 + n) * 32 + c32) * 16 + l;
                gb_Pp[base]          = __float2bfloat16_rn(acc[mt][nt][0]);
                gb_Pp[base + 16]     = __float2bfloat16_rn(acc[mt][nt][1]);  // c32+1
                gb_Pp[base + 8]      = __float2bfloat16_rn(acc[mt][nt][2]);  // l+8
                gb_Pp[base + 16 + 8] = __float2bfloat16_rn(acc[mt][nt][3]);
            }
    }
}

// ---- LSE merge helper ----
__device__ __forceinline__ void lsemerge(float& m, float& s, float om, float os) {
    float M = fmaxf(m, om);
    if (M == -INFINITY) { s = 0.0f; return; }
    float t1 = (m == -INFINITY) ? 0.0f : s * __expf(m - M);
    float t2 = (om == -INFINITY) ? 0.0f : os * __expf(om - M);
    m = M; s = t1 + t2;
}

// ---- scores = hn @ W_vocab + b : fused LSE partials + target harvest ----
__global__ __launch_bounds__(256) void gemm_vocab(const float* __restrict__ bv,
                                                  const int* __restrict__ captions) {
    int row0 = blockIdx.y * 128, col0 = blockIdx.x * 128;
    BFG_SMEM;
    BfgIdx ix;
    float acc[2][8][4] = {};
    BfgLoader ld;
    ld.a0 = gb_hn + (size_t)(row0 + ix.am) * H_ + ix.ag * 8;
    ld.a1 = ld.a0 + (size_t)64 * H_;
    int bcol = col0 + ix.bg * 8;
    ld.bsz = (bcol + 8 <= V_) ? 16u : 0u;
    ld.b0 = gb_Wv + (size_t)ix.bks * V_ + ((bcol + 8 <= V_) ? bcol : 0);
    ld.b1 = ld.b0 + (size_t)16 * V_;
    ld.aoff0 = ix.aoff0; ld.aoff1 = ix.aoff1; ld.boff0 = ix.boff0; ld.boff1 = ix.boff1;
    ld.bstep = (size_t)32 * V_;
    bfg_run(ld, H_ / 32, sA0, sB0, ix.lane, ix.wm, ix.wn, acc);
    int eg = ix.lane >> 2, ec = (ix.lane & 3) * 2;
    float bvr[8][2];
#pragma unroll
    for (int nt = 0; nt < 8; nt++) {
        int col = col0 + ix.wn * 64 + nt * 8 + ec;
        bvr[nt][0] = (col < V_) ? bv[col] : 0.0f;
        bvr[nt][1] = (col + 1 < V_) ? bv[col + 1] : 0.0f;
    }
#pragma unroll
    for (int mt = 0; mt < 2; mt++)
#pragma unroll
        for (int qn = 0; qn < 2; qn++) {
            int row = row0 + ix.wm * 32 + mt * 16 + eg + 8 * qn;
            int tgt = captions[(row >> 5) * TCAP + (row & 31) + 1];
            float vals[16];
            float m = -INFINITY;
#pragma unroll
            for (int nt = 0; nt < 8; nt++)
#pragma unroll
                for (int j = 0; j < 2; j++) {
                    int col = col0 + ix.wn * 64 + nt * 8 + ec + j;
                    float v = acc[mt][nt][2 * qn + j] + bvr[nt][j];
                    vals[nt * 2 + j] = v;
                    if (col < V_) {
                        m = fmaxf(m, v);
                        if (col == tgt) g_stgt[row] = v;
                    }
                }
            float s = 0.0f;
#pragma unroll
            for (int nt = 0; nt < 8; nt++)
#pragma unroll
                for (int j = 0; j < 2; j++) {
                    int col = col0 + ix.wn * 64 + nt * 8 + ec + j;
                    if (col < V_)
                        s += __expf(vals[nt * 2 + j] - m);
                }
#pragma unroll
            for (int off = 1; off <= 2; off <<= 1) {
                float om = __shfl_xor_sync(0xffffffffu, m, off);
                float os = __shfl_xor_sync(0xffffffffu, s, off);
                lsemerge(m, s, om, os);
            }
            if ((ix.lane & 3) == 0)
                g_lsep[(size_t)row * NLSE + blockIdx.x * 2 + ix.wn] = make_float2(m, s);
        }
}

// ---- loss: merge LSE partials, nll on targets ----
__global__ __launch_bounds__(256) void loss_f(const int* __restrict__ captions,
                                              float* __restrict__ out) {
    int r = blockIdx.x * 32 + (threadIdx.x >> 3);
    int j8 = threadIdx.x & 7;
    float m = -INFINITY, s = 0.0f;
    for (int j = j8; j < NLSE; j += 8) {
        float2 p = g_lsep[(size_t)r * NLSE + j];
        lsemerge(m, s, p.x, p.y);
    }
#pragma unroll
    for (int off = 1; off <= 4; off <<= 1) {
        float om = __shfl_xor_sync(0xffffffffu, m, off);
        float os = __shfl_xor_sync(0xffffffffu, s, off);
        lsemerge(m, s, om, os);
    }
    if (j8 == 0) {
        int n = r >> 5, t = r & 31;
        int tgt = captions[n * TCAP + t + 1];
        if (tgt != 0) {
            float nll = logf(s) + m - g_stgt[r];
            atomicAdd(out, nll * (1.0f / (float)N_));
        }
    }
}

// ================= persistent RNN loop =================
// smem: Wh 81920 | h 3x32768 | zx 16384 | ws 8192 | red 1536
#define SM_WH   0
#define SM_H    81920
#define SM_ZX   180224
#define SM_WS   196608
#define SM_RED  204800
#define SM_TOT  206336

// contention-free flag barrier: 1 flag / 32B sector
__device__ __forceinline__ void gbar(unsigned& gen) {
    gen++;
    __syncthreads();
    __threadfence();
    if (threadIdx.x == 0) __stcg(&g_flags[blockIdx.x * 8], gen);
    if (threadIdx.x < 32) {
        for (;;) {
            unsigned v0 = __ldcg(&g_flags[threadIdx.x * 8]);
            unsigned v1 = __ldcg(&g_flags[(threadIdx.x + 32) * 8]);
            unsigned v2 = __ldcg(&g_flags[(threadIdx.x + 64) * 8]);
            unsigned v3 = __ldcg(&g_flags[(threadIdx.x + 96) * 8]);
            if (v0 >= gen && v1 >= gen && v2 >= gen && v3 >= gen) break;
        }
    }
    __threadfence();
    __syncthreads();
}

__global__ __launch_bounds__(256, 1) void rnn_loop() {
    const int tid = threadIdx.x, bid = blockIdx.x;
    const int lane = tid & 31, w = tid >> 5;
    const int l15 = lane & 15, lhi = lane >> 4;
    uint32_t smb = (uint32_t)__cvta_generic_to_shared(sm_raw);
    uint32_t whb = smb + SM_WH, hb = smb + SM_H;
    float* sZX = (float*)(sm_raw + SM_ZX);
    float* sWs = (float*)(sm_raw + SM_WS);
    float* sRed = (float*)(sm_raw + SM_RED);

    for (int i = tid; i < 4096; i += 256) {
        int k = i >> 2, g = i & 3;
        cpa16(whb + (uint32_t)k * 80 + g * 16,
              gb_Wh + (size_t)k * H4_ + g * 1024 + bid * 8);
    }
    cp_commit(); cp_wait0();
    __syncthreads();

    float creg[2][2];
#pragma unroll
    for (int qn = 0; qn < 2; qn++) {
        int n = 16 * w + (lane >> 2) + 8 * qn;
#pragma unroll
        for (int qh = 0; qh < 2; qh++)
            creg[qn][qh] = g_h0[n * H_ + bid * 8 + (lane & 3) * 2 + qh];
    }

    unsigned gen = 0;

    // score indexing for sample n == bid
    const int sc_part = tid >> 4;         // 0..15 : which 8-dim slice of the chunk
    const int sc_l = tid & 15;            // which attention location l
    const uint32_t sc_soff = (uint32_t)bid * 256 + (uint32_t)((sc_part & 8) << 4) +
                             (uint32_t)(((sc_part & 7) ^ (bid & 7)) << 4);

    auto issue_h = [&](const __nv_bfloat16* hsrc, int kc, uint32_t dst) {
#pragma unroll
        for (int i = 0; i < 8; i++) {
            int id = tid + 256 * i;
            int n = id >> 4, g = id & 15;
            uint32_t off = (uint32_t)n * 256 + ((g & 8) << 4) + ((((g & 7) ^ (n & 7))) << 4);
            cpa16(dst + off, hsrc + (size_t)n * H_ + kc * 128 + g * 8);
        }
        cp_commit();
    };

    for (int t = 0; t < T_; t++) {
        const int cur = t & 1, nxt = cur ^ 1;
        const __nv_bfloat16* hsrc = gb_hbuf[cur];

        // ---- GEMM z = h @ Wh-slice + in-stream attention score for n=bid ----
        issue_h(hsrc, 0, hb);
        issue_h(hsrc, 1, hb + 32768);
        float acc[4][4] = {};
        float scacc = 0.0f;
        for (int kc = 0; kc < 8; kc++) {
            int b = kc % 3;
            if (kc < 7) cp_wait1(); else cp_wait0();
            __syncthreads();
            if (kc + 2 < 8)
                issue_h(hsrc, kc + 2, hb + (uint32_t)((kc + 2) % 3) * 32768);
            uint32_t hbase = hb + (uint32_t)b * 32768;
            int n_ld = 16 * w + l15;
#pragma unroll
            for (int k16 = 0; k16 < 8; k16++) {
                int cf = 2 * k16 + lhi;
                unsigned af[4];
                ldsm4(hbase + (uint32_t)n_ld * 256 + ((cf & 8) << 4) +
                          (uint32_t)(((cf & 7) ^ (n_ld & 7)) << 4),
                      af[0], af[1], af[2], af[3]);
                int kg = kc * 8 + k16;
                uint32_t brow = whb + (uint32_t)(kg * 16 + l15) * 80;
                unsigned b0, b1, b2, b3, b4, b5, b6, b7;
                ldsm4t(brow + (uint32_t)(lhi << 4), b0, b1, b2, b3);
                ldsm4t(brow + (uint32_t)((2 + lhi) << 4), b4, b5, b6, b7);
                bmma(acc[0], af, b0, b1);
                bmma(acc[1], af, b2, b3);
                bmma(acc[2], af, b4, b5);
                bmma(acc[3], af, b6, b7);
            }
            // score accumulation: h[bid][kc*128 + sc_part*8 .. +8] x A[bid][..][sc_l]
            {
                uint4 hv4 = *(const uint4*)(sm_raw + SM_H + (size_t)b * 32768 + sc_soff);
                const __nv_bfloat162* hh = (const __nv_bfloat162*)&hv4;
                int hk0 = kc * 128 + sc_part * 8;
                const float* Ab = &g_A[((size_t)bid * H_ + hk0) * L_ + sc_l];
#pragma unroll
                for (int j = 0; j < 4; j++) {
                    float2 f = __bfloat1622float2(hh[j]);
                    scacc = fmaf(f.x, Ab[(2 * j) * L_], scacc);
                    scacc = fmaf(f.y, Ab[(2 * j + 1) * L_], scacc);
                }
            }
        }
        __syncthreads();

        // ---- local score reduce + softmax -> g_w[bid] ----
        sWs[sc_part * 16 + sc_l] = scacc;
        __syncthreads();
        if (tid < 16) {
            float s = 0.0f;
#pragma unroll
            for (int p = 0; p < 16; p++) s += sWs[p * 16 + tid];
            sRed[tid] = s * 0.03125f;
        }
        __syncthreads();
        if (tid == 0) {
            float mx = -INFINITY;
#pragma unroll
            for (int l = 0; l < 16; l++) mx = fmaxf(mx, sRed[l]);
            float se = 0.0f;
            float ev[16];
#pragma unroll
            for (int l = 0; l < 16; l++) { ev[l] = __expf(sRed[l] - mx); se += ev[l]; }
            float inv = 1.0f / se;
#pragma unroll
            for (int l = 0; l < 16; l++) g_w[bid * 16 + l] = ev[l] * inv;
        }

        // ---- preload xproj (permuted layout: fully coalesced) ----
        {
            const float* xp = g_xproj + ((size_t)t * NBLK + bid) * 32;
            for (int v = tid; v < 4096; v += 256) {
                int n = v >> 5, c32 = v & 31;
                sZX[v] = xp[((size_t)n * T_) * (NBLK * 32) + c32];
            }
        }

        // ---- barrier publishes g_w (all samples) ----
        gbar(gen);

        // ---- zx += w . Pp (bf16, [n][c32][l] layout) ----
        for (int i = tid; i < 2048; i += 256) sWs[i] = __ldcg(&g_w[i]);
        __syncthreads();
        for (int v = tid; v < 4096; v += 256) {
            int n = v >> 5, c32 = v & 31;
            float a = sZX[v];
            const __nv_bfloat16* pp = &gb_Pp[(((size_t)bid * 128 + n) * 32 + c32) * 16];
            uint4 p0 = *(const uint4*)pp;
            uint4 p1 = *(const uint4*)(pp + 8);
            const float* wn_ = &sWs[n * 16];
            const __nv_bfloat162* h2a = (const __nv_bfloat162*)&p0;
            const __nv_bfloat162* h2b = (const __nv_bfloat162*)&p1;
#pragma unroll
            for (int j = 0; j < 4; j++) {
                float2 fa = __bfloat1622float2(h2a[j]);
                float2 fb = __bfloat1622float2(h2b[j]);
                a = fmaf(wn_[2 * j], fa.x, a);
                a = fmaf(wn_[2 * j + 1], fa.y, a);
                a = fmaf(wn_[8 + 2 * j], fb.x, a);
                a = fmaf(wn_[8 + 2 * j + 1], fb.y, a);
            }
            sZX[v] = a;
        }
        __syncthreads();

        // ---- gates ----
#pragma unroll
        for (int qn = 0; qn < 2; qn++) {
            int n = 16 * w + (lane >> 2) + 8 * qn;
#pragma unroll
            for (int qh = 0; qh < 2; qh++) {
                int hh = (lane & 3) * 2 + qh;
                int q = 2 * qn + qh;
                float zi = acc[0][q] + sZX[n * 32 + hh];
                float zf = acc[1][q] + sZX[n * 32 + 8 + hh];
                float zo = acc[2][q] + sZX[n * 32 + 16 + hh];
                float zg = acc[3][q] + sZX[n * 32 + 24 + hh];
                float c = sigfast(zf) * creg[qn][qh] + sigfast(zi) * tanhfast(zg);
                float hv = sigfast(zo) * tanhfast(c);
                creg[qn][qh] = c;
                __nv_bfloat16 hb16 = __float2bfloat16_rn(hv);
                gb_hbuf[nxt][n * H_ + bid * 8 + hh] = hb16;
                gb_hn[((size_t)n * T_ + t) * H_ + bid * 8 + hh] = hb16;
            }
        }

        // ---- barrier publishes h(t) ----
        if (t < T_ - 1) gbar(gen);
    }
}

// ---------------- launch ----------------
extern "C" void kernel_launch(void* const* d_in, const int* in_sizes, int n_in,
                              void* d_out, int out_size) {
    const float* features = (const float*)d_in[0];
    const int*   captions = (const int*)d_in[1];
    const float* W_embed  = (const float*)d_in[2];
    const float* W_proj   = (const float*)d_in[3];
    const float* b_proj   = (const float*)d_in[4];
    const float* Wx       = (const float*)d_in[5];
    const float* Wh       = (const float*)d_in[6];
    const float* Wattn    = (const float*)d_in[7];
    const float* b        = (const float*)d_in[8];
    const float* W_vocab  = (const float*)d_in[9];
    const float* b_vocab  = (const float*)d_in[10];
    float* out = (float*)d_out;

    cudaFuncSetAttribute(rnn_loop, cudaFuncAttributeMaxDynamicSharedMemorySize, SM_TOT);

    prep_all<<<PREP_BLKS, 256>>>(W_embed, Wx, Wh, Wattn, W_vocab,
                                 features, W_proj, b_proj, out);            // our 0 (g2)
    gemm_embedP<<<1536, 256>>>(captions, b);                                // our 1 (g3)
    rnn_loop<<<NBLK, 256, SM_TOT>>>();                                      // our 2 (g4)
    gemm_vocab<<<dim3(NBX, (N_ * T_) / 128), 256>>>(b_vocab, captions);     // our 3 (g5) -> ncu
    loss_f<<<(N_ * T_) / 32, 256>>>(captions, out);                         // our 4 (g6)
}